// round 10
// baseline (speedup 1.0000x reference)
#include <cuda_runtime.h>
#include <cstdint>

// MeanAggregator: out[i] = sum_{j in edges[i]} nodes[edges[i][j]] / n_nodes
// Shapes: N = 40000, DEG = 16, D = 128 (fp32); edges buffer is int32
// (JAX downgrades int64 -> int32 without x64 mode).
//
// Strategy (R8 design, resubmitted): ptxas pinned regs at 32 in R4-R7 by
// hoisting FADD consumers into the load window, collapsing MLP to ~4.
// Here BOTH the 16 gathers and the first reduction level are volatile asm,
// so the volatile program order is: 16 loads, THEN 8 adds. All 64 payload
// registers stay live across the load window -> true per-warp MLP = 16.

#define D_FEAT 128
#define D_VEC (D_FEAT / 4)   // 32 float4 per row = 1 per lane
#define DEG_FAST 16

#define LDG128NC(dst, ptr)                                                   \
    asm volatile("ld.global.nc.v4.f32 {%0,%1,%2,%3}, [%4];"                  \
                 : "=f"(dst.x), "=f"(dst.y), "=f"(dst.z), "=f"(dst.w)        \
                 : "l"(ptr))

// First-level pairwise add, volatile so it cannot move into the load window.
#define VADD4(d, a, b)                                                       \
    asm volatile("add.f32 %0, %4, %8;\n\t"                                   \
                 "add.f32 %1, %5, %9;\n\t"                                   \
                 "add.f32 %2, %6, %10;\n\t"                                  \
                 "add.f32 %3, %7, %11;"                                      \
                 : "=f"(d.x), "=f"(d.y), "=f"(d.z), "=f"(d.w)                \
                 : "f"(a.x), "f"(a.y), "f"(a.z), "f"(a.w),                   \
                   "f"(b.x), "f"(b.y), "f"(b.z), "f"(b.w))

__global__ __launch_bounds__(256) void gather_mean_mlp16_kernel(
    const float4* __restrict__ nodes,   // [n_nodes * 32] float4
    const int* __restrict__ edges,      // [n_nodes * deg] int32
    float4* __restrict__ out,           // [n_nodes * 32] float4
    int n_nodes, int deg, float inv_n)
{
    const int warp_id = (blockIdx.x * blockDim.x + threadIdx.x) >> 5;
    const int lane = threadIdx.x & 31;
    if (warp_id >= n_nodes) return;

    float4 acc = make_float4(0.f, 0.f, 0.f, 0.f);

    if (deg == DEG_FAST) {
        // Index fetch: 4 x int4 (uniform across warp -> broadcast LDG).
        const int4* e4 = (const int4*)(edges + (long long)warp_id * DEG_FAST);
        int idx[DEG_FAST];
#pragma unroll
        for (int q = 0; q < 4; ++q) {
            int4 a = __ldg(&e4[q]);
            idx[q * 4 + 0] = a.x; idx[q * 4 + 1] = a.y;
            idx[q * 4 + 2] = a.z; idx[q * 4 + 3] = a.w;
        }

        // 16 back-to-back gathers; consumers below are volatile too, so
        // nothing can be scheduled inside this window.
        float4 v[DEG_FAST];
#pragma unroll
        for (int j = 0; j < DEG_FAST; ++j) {
            const float4* p = nodes + (size_t)((unsigned)idx[j] * D_VEC + lane);
            LDG128NC(v[j], p);
        }

        // Level 1 (volatile): 16 -> 8.
        float4 s[8];
#pragma unroll
        for (int j = 0; j < 8; ++j) {
            VADD4(s[j], v[2 * j], v[2 * j + 1]);
        }

        // Remaining levels: plain C (all loads already issued).
        float4 t[4];
#pragma unroll
        for (int j = 0; j < 4; ++j) {
            t[j].x = s[2 * j].x + s[2 * j + 1].x;
            t[j].y = s[2 * j].y + s[2 * j + 1].y;
            t[j].z = s[2 * j].z + s[2 * j + 1].z;
            t[j].w = s[2 * j].w + s[2 * j + 1].w;
        }
        acc.x = (t[0].x + t[1].x) + (t[2].x + t[3].x);
        acc.y = (t[0].y + t[1].y) + (t[2].y + t[3].y);
        acc.z = (t[0].z + t[1].z) + (t[2].z + t[3].z);
        acc.w = (t[0].w + t[1].w) + (t[2].w + t[3].w);
    } else {
        // Generic fallback: unroll by 4.
        const int* e = edges + (long long)warp_id * deg;
        int j = 0;
        for (; j + 4 <= deg; j += 4) {
            int i0 = __ldg(&e[j + 0]);
            int i1 = __ldg(&e[j + 1]);
            int i2 = __ldg(&e[j + 2]);
            int i3 = __ldg(&e[j + 3]);
            float4 v0 = __ldg(&nodes[i0 * D_VEC + lane]);
            float4 v1 = __ldg(&nodes[i1 * D_VEC + lane]);
            float4 v2 = __ldg(&nodes[i2 * D_VEC + lane]);
            float4 v3 = __ldg(&nodes[i3 * D_VEC + lane]);
            acc.x += (v0.x + v1.x) + (v2.x + v3.x);
            acc.y += (v0.y + v1.y) + (v2.y + v3.y);
            acc.z += (v0.z + v1.z) + (v2.z + v3.z);
            acc.w += (v0.w + v1.w) + (v2.w + v3.w);
        }
        for (; j < deg; ++j) {
            int i0 = __ldg(&e[j]);
            float4 v = __ldg(&nodes[i0 * D_VEC + lane]);
            acc.x += v.x; acc.y += v.y; acc.z += v.z; acc.w += v.w;
        }
    }

    out[(long long)warp_id * D_VEC + lane] =
        make_float4(acc.x * inv_n, acc.y * inv_n, acc.z * inv_n, acc.w * inv_n);
}

extern "C" void kernel_launch(void* const* d_in, const int* in_sizes, int n_in,
                              void* d_out, int out_size)
{
    const float4* nodes = (const float4*)d_in[0];
    const int* edges = (const int*)d_in[1];
    float4* out = (float4*)d_out;

    const int n_nodes = in_sizes[0] / D_FEAT;
    const int deg = in_sizes[1] / n_nodes;
    const float inv_n = 1.0f / (float)n_nodes;

    const int threads = 256;
    const int warps_per_block = threads / 32;
    const int blocks = (n_nodes + warps_per_block - 1) / warps_per_block;  // 5000
    gather_mean_mlp16_kernel<<<blocks, threads>>>(nodes, edges, out,
                                                  n_nodes, deg, inv_n);
}

// round 11
// speedup vs baseline: 1.0270x; 1.0270x over previous
#include <cuda_runtime.h>
#include <cstdint>

// MeanAggregator: out[i] = sum_{j in edges[i]} nodes[edges[i][j]] / n_nodes
// Shapes: N = 40000, DEG = 16, D = 128 (fp32); edges buffer is int32.
//
// R11: LDG.128 gathers span 512B = 4 L1 wavefronts of ONE instruction, which
// replay at 2.07 cyc/wf -> hard ceiling 0.48 lines/cyc (~18.8us); measured
// 0.39. Scalar LDG.32 makes every warp load exactly one 128B line (1.0
// cyc/wf, no replay). New floor is LSU issue: 17.3k LDG/SM * 1.82 ~ 16.5us.
// Thread t owns features {t, t+32, t+64, t+96}; 4 loads/neighbor.

#define D_FEAT 128
#define DEG_FAST 16

__global__ __launch_bounds__(256) void gather_mean_s32_kernel(
    const float* __restrict__ nodes,    // [n_nodes * 128] float
    const int* __restrict__ edges,      // [n_nodes * deg] int32
    float* __restrict__ out,            // [n_nodes * 128] float
    int n_nodes, int deg, float inv_n)
{
    const int warp_id = (blockIdx.x * blockDim.x + threadIdx.x) >> 5;
    const int lane = threadIdx.x & 31;
    if (warp_id >= n_nodes) return;

    float a0 = 0.f, a1 = 0.f, a2 = 0.f, a3 = 0.f;

    if (deg == DEG_FAST) {
        // Index fetch: 4 x int4 (uniform across warp -> broadcast LDG).
        const int4* e4 = (const int4*)(edges + (long long)warp_id * DEG_FAST);
        int idx[DEG_FAST];
#pragma unroll
        for (int q = 0; q < 4; ++q) {
            int4 a = __ldg(&e4[q]);
            idx[q * 4 + 0] = a.x; idx[q * 4 + 1] = a.y;
            idx[q * 4 + 2] = a.z; idx[q * 4 + 3] = a.w;
        }

        // 64 scalar gathers: each warp-LDG.32 covers one full 128B line
        // (32 lanes x 4B contiguous) -> 1.0 cyc/wavefront L1 service,
        // no within-instruction replay.
#pragma unroll
        for (int j = 0; j < DEG_FAST; ++j) {
            const float* row = nodes + (size_t)(unsigned)idx[j] * D_FEAT + lane;
            float v0 = __ldg(row);
            float v1 = __ldg(row + 32);
            float v2 = __ldg(row + 64);
            float v3 = __ldg(row + 96);
            a0 += v0; a1 += v1; a2 += v2; a3 += v3;
        }
    } else {
        const int* e = edges + (long long)warp_id * deg;
        for (int j = 0; j < deg; ++j) {
            int i0 = __ldg(&e[j]);
            const float* row = nodes + (size_t)(unsigned)i0 * D_FEAT + lane;
            a0 += __ldg(row);
            a1 += __ldg(row + 32);
            a2 += __ldg(row + 64);
            a3 += __ldg(row + 96);
        }
    }

    // 4 coalesced scalar stores (each = one 128B line per warp).
    float* o = out + (long long)warp_id * D_FEAT + lane;
    o[0]  = a0 * inv_n;
    o[32] = a1 * inv_n;
    o[64] = a2 * inv_n;
    o[96] = a3 * inv_n;
}

extern "C" void kernel_launch(void* const* d_in, const int* in_sizes, int n_in,
                              void* d_out, int out_size)
{
    const float* nodes = (const float*)d_in[0];
    const int* edges = (const int*)d_in[1];
    float* out = (float*)d_out;

    const int n_nodes = in_sizes[0] / D_FEAT;
    const int deg = in_sizes[1] / n_nodes;
    const float inv_n = 1.0f / (float)n_nodes;

    // One warp per node, 8 warps (256 threads) per block.
    const int threads = 256;
    const int warps_per_block = threads / 32;
    const int blocks = (n_nodes + warps_per_block - 1) / warps_per_block;  // 5000
    gather_mean_s32_kernel<<<blocks, threads>>>(nodes, edges, out,
                                                n_nodes, deg, inv_n);
}